// round 4
// baseline (speedup 1.0000x reference)
#include <cuda_runtime.h>
#include <cuda_bf16.h>
#include <math.h>
#include <stdint.h>

#define BB 2
#define CC 64
#define HH 64
#define WW 96
#define C4C 256
#define HWp (HH*WW)          // 6144
#define NPIX (BB*HH*WW)      // 12288
#define NTOT (BB*CC*HH*WW)   // 786432
#define WSZ 8
#define PP 4

// ---------------- packed f32x2 helpers (sm_100+) ----------------
__device__ __forceinline__ uint64_t pack2(float lo, float hi) {
    uint64_t r;
    asm("mov.b64 %0, {%1, %2};" : "=l"(r) : "f"(lo), "f"(hi));
    return r;
}
__device__ __forceinline__ void unpack2(uint64_t v, float& lo, float& hi) {
    asm("mov.b64 {%0, %1}, %2;" : "=f"(lo), "=f"(hi) : "l"(v));
}
__device__ __forceinline__ void ffma2(uint64_t& d, uint64_t a, uint64_t b) {
    asm("fma.rn.f32x2 %0, %1, %2, %0;" : "+l"(d) : "l"(a), "l"(b));
}

// ---------------- scratch (static device allocations) ----------------
__device__ float g_bn [2*BB*C4C*HWp];   // BN output, both sides
__device__ float g_y1 [2*BB*C4C*HWp];   // conv1 + leakyrelu
__device__ float g_res[2*BB*C4C*HWp];   // resblock output
__device__ float g_Q  [NTOT];           // NHWC  [b][h][w][c]
__device__ float g_K  [NTOT];
__device__ float g_xl [NTOT];           // x_left NHWC
__device__ float g_xr [NTOT];
__device__ float g_oL [NTOT];           // out_left NHWC (pre-transpose)
__device__ float g_oR [NTOT];

// ---------------- BN (eval) ----------------
__global__ void bn_kernel(const float* __restrict__ cl, const float* __restrict__ cr,
                          const float* __restrict__ g, const float* __restrict__ bt,
                          const float* __restrict__ m, const float* __restrict__ v) {
    int i = blockIdx.x * blockDim.x + threadIdx.x;
    if (i >= BB*C4C*HWp) return;
    int ch = (i / HWp) % C4C;
    float sc = g[ch] * rsqrtf(v[ch] + 1e-5f);
    float sh = bt[ch] - m[ch] * sc;
    g_bn[i]                 = fmaf(cl[i], sc, sh);
    g_bn[i + BB*C4C*HWp]    = fmaf(cr[i], sc, sh);
}

// ---------------- NCHW -> NHWC transpose of x_left/x_right ----------------
__global__ void transpose_in_kernel(const float* __restrict__ in, int which) {
    __shared__ float tile[32][33];
    float* out = which ? g_xr : g_xl;
    int b = blockIdx.z;
    const float* inb = in + (size_t)b * CC * HWp;
    float* outb      = out + (size_t)b * HWp * CC;
    int p0 = blockIdx.x * 32;
    int c0 = blockIdx.y * 32;
    int tx = threadIdx.x, ty = threadIdx.y;
    #pragma unroll
    for (int i = 0; i < 32; i += 8)
        tile[ty + i][tx] = inb[(size_t)(c0 + ty + i) * HWp + p0 + tx];
    __syncthreads();
    #pragma unroll
    for (int i = 0; i < 32; i += 8)
        outb[(size_t)(p0 + ty + i) * CC + c0 + tx] = tile[tx][ty + i];
}

// ---------------- NHWC -> NCHW output transpose ----------------
__global__ void transpose_out_kernel(float* __restrict__ outbase, int which) {
    __shared__ float tile[32][33];
    const float* in = which ? g_oR : g_oL;
    float* out = outbase + (size_t)which * NTOT;
    int b = blockIdx.z;
    const float* inb = in + (size_t)b * HWp * CC;
    float* outb      = out + (size_t)b * CC * HWp;
    int c0 = blockIdx.x * 32;
    int p0 = blockIdx.y * 32;
    int tx = threadIdx.x, ty = threadIdx.y;
    #pragma unroll
    for (int i = 0; i < 32; i += 8)
        tile[ty + i][tx] = inb[(size_t)(p0 + ty + i) * CC + c0 + tx];
    __syncthreads();
    #pragma unroll
    for (int i = 0; i < 32; i += 8)
        outb[(size_t)(c0 + ty + i) * HWp + p0 + tx] = tile[tx][ty + i];
}

// ---------------- grouped 3x3 conv (groups=4), f32x2 packed math ----------------
// STAGE 0: in=g_bn, out=g_y1, LeakyReLU(0.1)
// STAGE 1: in=g_y1, out=g_res, residual add g_bn
template<int STAGE>
__global__ __launch_bounds__(256)
void conv3x3_kernel(const float* __restrict__ wgt, const float* __restrict__ bias) {
    __shared__ float  in_s[8][34][34];
    __shared__ float2 w_s[16][8][9];   // duplicated {w,w} for packed FMA

    const float* in = (STAGE == 0) ? g_bn : g_y1;
    float* out      = (STAGE == 0) ? g_y1 : g_res;

    int z = blockIdx.z;
    int oc4  = z & 3;
    int g    = (z >> 2) & 3;
    int b    = (z >> 4) & 1;
    int side = z >> 5;
    int h0 = blockIdx.y * 32, w0 = blockIdx.x * 32;

    const float* inb = in + ((size_t)(side*BB + b) * C4C + g*64) * HWp;
    int ocg = g*64 + oc4*16;

    uint64_t acc01[16], acc23[16];
    #pragma unroll
    for (int o = 0; o < 16; o++) { acc01[o] = 0ull; acc23[o] = 0ull; }

    int tid = threadIdx.x;
    int tx = tid & 31, ty = tid >> 5;

    for (int icb = 0; icb < 64; icb += 8) {
        __syncthreads();
        // input tile 8 x 34 x 34 (halo=1)
        for (int idx = tid; idx < 8*34*34; idx += 256) {
            int ic  = idx / (34*34);
            int rem = idx % (34*34);
            int r = rem / 34, cc2 = rem % 34;
            int gy = h0 + r - 1, gx = w0 + cc2 - 1;
            float val = 0.f;
            if (gy >= 0 && gy < HH && gx >= 0 && gx < WW)
                val = inb[(size_t)(icb + ic) * HWp + gy * WW + gx];
            in_s[ic][r][cc2] = val;
        }
        // weights 16 oc x 8 ic x 9, duplicated into float2
        for (int idx = tid; idx < 16*8*9; idx += 256) {
            int oc = idx / 72;
            int rem = idx % 72;
            int ic = rem / 9, kk = rem % 9;
            float wv = wgt[((size_t)(ocg + oc) * 64 + icb + ic) * 9 + kk];
            w_s[oc][ic][kk] = make_float2(wv, wv);
        }
        __syncthreads();

        #pragma unroll 1
        for (int ic = 0; ic < 8; ic++) {
            #pragma unroll
            for (int kh = 0; kh < 3; kh++) {
                #pragma unroll
                for (int kw = 0; kw < 3; kw++) {
                    float i0 = in_s[ic][ty +  0 + kh][tx + kw];
                    float i1 = in_s[ic][ty +  8 + kh][tx + kw];
                    float i2 = in_s[ic][ty + 16 + kh][tx + kw];
                    float i3 = in_s[ic][ty + 24 + kh][tx + kw];
                    uint64_t a01 = pack2(i0, i1);
                    uint64_t a23 = pack2(i2, i3);
                    const uint64_t* wp = (const uint64_t*)&w_s[0][ic][kh*3 + kw];
                    #pragma unroll
                    for (int oc = 0; oc < 16; oc++) {
                        uint64_t wv = wp[(size_t)oc * (8*9)];
                        ffma2(acc01[oc], a01, wv);
                        ffma2(acc23[oc], a23, wv);
                    }
                }
            }
        }
    }

    #pragma unroll
    for (int oc = 0; oc < 16; oc++) {
        float bv = bias[ocg + oc];
        float v0, v1, v2, v3;
        unpack2(acc01[oc], v0, v1);
        unpack2(acc23[oc], v2, v3);
        float vv[4] = {v0, v1, v2, v3};
        #pragma unroll
        for (int p = 0; p < 4; p++) {
            float val = vv[p] + bv;
            if (STAGE == 0) val = val > 0.f ? val : 0.1f * val;   // LeakyReLU
            size_t oi = ((size_t)(side*BB + b) * C4C + ocg + oc) * HWp
                      + (size_t)(h0 + ty + p*8) * WW + (w0 + tx);
            if (STAGE == 1) val += g_bn[oi];                      // residual
            out[oi] = val;
        }
    }
}

// ---------------- grouped 1x1 conv -> Q/K in NHWC (smem-tiled, per-group) ----------------
// Block: 256 threads = 16 oc x 16 pixel-quads (4 px each). Grid: (pixel tiles, group, side)
__global__ __launch_bounds__(256)
void conv1x1_kernel(const float* __restrict__ bq_w, const float* __restrict__ bq_b,
                    const float* __restrict__ bs_w, const float* __restrict__ bs_b) {
    __shared__ float in_s[64][64];      // 16 KB: 64 group-channels x 64 pixels
    __shared__ float w_sh[16][64];      // 4 KB:  16 oc x 64 ic

    int side = blockIdx.z;
    int g    = blockIdx.y;
    int p0   = blockIdx.x * 64;         // tile start within [0, BB*HWp)
    int b    = p0 / HWp;
    int tid  = threadIdx.x;

    const float* wsrc = side ? bs_w : bq_w;
    const float* bsrc = side ? bs_b : bq_b;

    // stage weights: oc in [g*16, g*16+16), ic local 0..63
    for (int i = tid; i < 16*64; i += 256) {
        int oc = i >> 6, ic = i & 63;
        w_sh[oc][ic] = wsrc[(g*16 + oc)*64 + ic];
    }

    // stage input tile: 64 group channels x 64 consecutive pixels (coalesced)
    const float* resb = g_res + ((size_t)(side*BB + b) * C4C + g*64) * HWp + (p0 - b*HWp);
    for (int i = tid; i < 64*64; i += 256) {
        int ch = i >> 6, px = i & 63;
        in_s[ch][px] = resb[(size_t)ch * HWp + px];
    }
    __syncthreads();

    int oc = tid & 15;          // local output channel (0..15)
    int pq = tid >> 4;          // pixel quad (0..15), 4 px each

    uint64_t acc[2] = {0ull, 0ull};
    #pragma unroll 8
    for (int ic = 0; ic < 64; ic++) {
        float wv = w_sh[oc][ic];
        uint64_t ww = pack2(wv, wv);
        const uint64_t* irow = (const uint64_t*)&in_s[ic][pq*4];
        ffma2(acc[0], irow[0], ww);
        ffma2(acc[1], irow[1], ww);
    }

    float bv = bsrc[g*16 + oc];
    float* o = side ? g_K : g_Q;
    int ocg = g*16 + oc;
    #pragma unroll
    for (int j = 0; j < 2; j++) {
        float lo, hi;
        unpack2(acc[j], lo, hi);
        int px = pq*4 + 2*j;
        o[(size_t)(p0 + px    ) * CC + ocg] = lo + bv;
        o[(size_t)(p0 + px + 1) * CC + ocg] = hi + bv;
    }
}

// ---------------- reductions ----------------
__device__ __forceinline__ float block2_max(float v, volatile float* red, int t) {
    #pragma unroll
    for (int o = 16; o; o >>= 1) v = fmaxf(v, __shfl_xor_sync(0xffffffffu, v, o));
    if ((t & 31) == 0) red[t >> 5] = v;
    __syncthreads();
    float r = fmaxf(red[0], red[1]);
    __syncthreads();
    return r;
}
__device__ __forceinline__ float block2_sum(float v, volatile float* red, int t) {
    #pragma unroll
    for (int o = 16; o; o >>= 1) v += __shfl_xor_sync(0xffffffffu, v, o);
    if ((t & 31) == 0) red[t >> 5] = v;
    __syncthreads();
    float r = red[0] + red[1];
    __syncthreads();
    return r;
}

// ---------------- attention: 1 block (64 threads) per pixel ----------------
__global__ __launch_bounds__(64)
void attn_kernel(const int* __restrict__ d_left, const int* __restrict__ d_right) {
    __shared__ __align__(16) float q_s[64];
    __shared__ __align__(16) float k_s[64];
    __shared__ float s1_s[64], s2_s[64];
    __shared__ int   cd_s[64];
    __shared__ float red[2];

    int pix = blockIdx.x;
    int b  = pix / HWp;
    int hp = pix % HWp;
    int h  = hp / WW, w = hp % WW;
    int t  = threadIdx.x;

    q_s[t] = g_Q[(size_t)pix * CC + t];
    k_s[t] = g_K[(size_t)pix * CC + t];

    int dl = d_left[pix], dr = d_right[pix];
    int c1 = max(w - dl, 0);
    int c2 = min(w + dr, WW - 1);
    bool rowok  = (h < HH - PP);
    bool valid1 = rowok && (c1 < WW - PP);
    bool valid2 = rowok && (c2 < WW - PP);
    __syncthreads();

    int a = t >> 3, bb2 = t & 7;
    int y  = h + a - PP;
    int x1 = c1 + bb2 - PP;
    int x2 = c2 + bb2 - PP;
    bool in1 = valid1 && (y >= 0) && (y < HH) && (x1 >= 0) && (x1 < WW);
    bool in2 = valid2 && (y >= 0) && (y < HH) && (x2 >= 0) && (x2 < WW);

    float r1 = 0.f, r2 = 0.f;
    if (in1) {
        const float4* kr = (const float4*)(g_K + ((size_t)b*HWp + (size_t)y*WW + x1) * CC);
        const float4* qv = (const float4*)q_s;
        #pragma unroll
        for (int i = 0; i < 16; i++) {
            float4 kv = kr[i]; float4 q4 = qv[i];
            r1 += q4.x*kv.x + q4.y*kv.y + q4.z*kv.z + q4.w*kv.w;
        }
    }
    if (in2) {
        const float4* qr = (const float4*)(g_Q + ((size_t)b*HWp + (size_t)y*WW + x2) * CC);
        const float4* k4v = (const float4*)k_s;
        #pragma unroll
        for (int i = 0; i < 16; i++) {
            float4 qv2 = qr[i]; float4 k4 = k4v[i];
            r2 += k4.x*qv2.x + k4.y*qv2.y + k4.z*qv2.z + k4.w*qv2.w;
        }
    }
    cd_s[t] = in1 ? (y * WW + x1) : -1;

    float m1 = block2_max(r1, red, t);
    float e1 = __expf(r1 - m1);
    float z1 = block2_sum(e1, red, t);
    float m2 = block2_max(r2, red, t);
    float e2 = __expf(r2 - m2);
    float z2 = block2_sum(e2, red, t);
    s1_s[t] = e1 / z1;
    s2_s[t] = e2 / z2;
    __syncthreads();

    const float* xrb = g_xr + (size_t)b * HWp * CC;
    const float* xlb = g_xl + (size_t)b * HWp * CC;
    float accL = 0.f, accR = 0.f;
    #pragma unroll 4
    for (int k = 0; k < 64; k++) {
        int cd = cd_s[k];
        if (cd >= 0) {
            accL = fmaf(s1_s[k], xrb[(size_t)cd * CC + t], accL);
            accR = fmaf(s2_s[k], xlb[(size_t)cd * CC + t], accR);
        }
    }
    float VL = (w - dl >= 0)     ? 1.f : 0.f;
    float VR = (w + dr <= WW-1)  ? 1.f : 0.f;
    size_t oi = (size_t)pix * CC + t;
    g_oL[oi] = xlb[(size_t)hp * CC + t] + VL * accL;
    g_oR[oi] = xrb[(size_t)hp * CC + t] + VR * accR;
}

// ---------------- launch ----------------
extern "C" void kernel_launch(void* const* d_in, const int* in_sizes, int n_in,
                              void* d_out, int out_size) {
    (void)n_in; (void)out_size;
    const float *xl, *xr, *cl, *cr, *bg, *bbeta, *bm, *bv;
    const float *w1, *b1, *w2, *b2, *bqw, *bqb, *bsw, *bsb;
    const int *dl, *dr;

    if (in_sizes[4] == BB*HH*WW) {
        xl  = (const float*)d_in[0];  xr  = (const float*)d_in[1];
        cl  = (const float*)d_in[2];  cr  = (const float*)d_in[3];
        dl  = (const int*)  d_in[4];  dr  = (const int*)  d_in[5];
        bg  = (const float*)d_in[6];  bbeta=(const float*)d_in[7];
        bm  = (const float*)d_in[8];  bv  = (const float*)d_in[9];
        w1  = (const float*)d_in[10]; b1  = (const float*)d_in[11];
        w2  = (const float*)d_in[12]; b2  = (const float*)d_in[13];
        bqw = (const float*)d_in[14]; bqb = (const float*)d_in[15];
        bsw = (const float*)d_in[16]; bsb = (const float*)d_in[17];
    } else {
        xl  = (const float*)d_in[0];  xr  = (const float*)d_in[1];
        cl  = (const float*)d_in[2];  cr  = (const float*)d_in[3];
        bg  = (const float*)d_in[4];  bbeta=(const float*)d_in[5];
        bm  = (const float*)d_in[6];  bv  = (const float*)d_in[7];
        w1  = (const float*)d_in[8];  b1  = (const float*)d_in[9];
        w2  = (const float*)d_in[10]; b2  = (const float*)d_in[11];
        bqw = (const float*)d_in[12]; bqb = (const float*)d_in[13];
        bsw = (const float*)d_in[14]; bsb = (const float*)d_in[15];
        dl  = (const int*)  d_in[16]; dr  = (const int*)  d_in[17];
    }

    dim3 tb(32, 8);

    bn_kernel<<<(BB*C4C*HWp + 255)/256, 256>>>(cl, cr, bg, bbeta, bm, bv);
    transpose_in_kernel<<<dim3(HWp/32, CC/32, BB), tb>>>(xl, 0);
    transpose_in_kernel<<<dim3(HWp/32, CC/32, BB), tb>>>(xr, 1);

    conv3x3_kernel<0><<<dim3(WW/32, HH/32, 64), 256>>>(w1, b1);
    conv3x3_kernel<1><<<dim3(WW/32, HH/32, 64), 256>>>(w2, b2);

    conv1x1_kernel<<<dim3(BB*HWp/64, 4, 2), 256>>>(bqw, bqb, bsw, bsb);

    attn_kernel<<<NPIX, 64>>>(dl, dr);

    transpose_out_kernel<<<dim3(CC/32, HWp/32, BB), tb>>>((float*)d_out, 0);
    transpose_out_kernel<<<dim3(CC/32, HWp/32, BB), tb>>>((float*)d_out, 1);
}

// round 6
// speedup vs baseline: 2.1164x; 2.1164x over previous
#include <cuda_runtime.h>
#include <cuda_bf16.h>
#include <math.h>
#include <stdint.h>

#define BB 2
#define CC 64
#define HH 64
#define WW 96
#define C4C 256
#define HWp (HH*WW)
#define NPIX (BB*HH*WW)
#define NTOT (BB*CC*HH*WW)
#define PP 4
#define SBG 16

// ---------------- scratch ----------------
__device__ float g_bn [SBG*64*HWp];
__device__ float g_res[SBG*64*HWp];
__device__ __align__(16) __nv_bfloat16 g_aH[SBG*HWp*64], g_aM[SBG*HWp*64];
__device__ __align__(16) __nv_bfloat16 g_yH[SBG*HWp*64], g_yM[SBG*HWp*64];
__device__ __align__(16) __nv_bfloat16 g_w1H[4*9*64*64], g_w1M[4*9*64*64];
__device__ __align__(16) __nv_bfloat16 g_w2H[4*9*64*64], g_w2M[4*9*64*64];
__device__ float g_Q[NTOT], g_K[NTOT], g_xl[NTOT], g_xr[NTOT], g_oL[NTOT], g_oR[NTOT];

__device__ __forceinline__ uint32_t smem_u32(const void* p) {
    uint32_t a;
    asm("{ .reg .u64 t; cvta.to.shared.u64 t, %1; cvt.u32.u64 %0, t; }" : "=r"(a) : "l"(p));
    return a;
}
__device__ __forceinline__ void ldm_x4(uint32_t* r, uint32_t addr) {
    asm volatile("ldmatrix.sync.aligned.m8n8.x4.shared.b16 {%0,%1,%2,%3}, [%4];"
        : "=r"(r[0]), "=r"(r[1]), "=r"(r[2]), "=r"(r[3]) : "r"(addr));
}
__device__ __forceinline__ void mma16816(float* d, const uint32_t* a, uint32_t b0, uint32_t b1) {
    asm volatile("mma.sync.aligned.m16n8k16.row.col.f32.bf16.bf16.f32 "
        "{%0,%1,%2,%3}, {%4,%5,%6,%7}, {%8,%9}, {%0,%1,%2,%3};"
        : "+f"(d[0]), "+f"(d[1]), "+f"(d[2]), "+f"(d[3])
        : "r"(a[0]), "r"(a[1]), "r"(a[2]), "r"(a[3]), "r"(b0), "r"(b1));
}

__device__ __forceinline__ void split2(float x, __nv_bfloat16& h, __nv_bfloat16& m) {
    h = __float2bfloat16_rn(x);
    m = __float2bfloat16_rn(x - __bfloat162float(h));
}

// ---------------- BN ----------------
__global__ void bn_kernel(const float* __restrict__ cl, const float* __restrict__ cr,
                          const float* __restrict__ g, const float* __restrict__ bt,
                          const float* __restrict__ m, const float* __restrict__ v) {
    int i = blockIdx.x * blockDim.x + threadIdx.x;
    if (i >= BB*C4C*HWp) return;
    int ch = (i / HWp) % C4C;
    float sc = g[ch] * rsqrtf(v[ch] + 1e-5f);
    float sh = bt[ch] - m[ch] * sc;
    g_bn[i]              = fmaf(cl[i], sc, sh);
    g_bn[i + BB*C4C*HWp] = fmaf(cr[i], sc, sh);
}

// ---------------- prep: g_bn NCHW -> 2-term bf16 NGHWC ----------------
__global__ __launch_bounds__(256)
void prep_input_kernel() {
    __shared__ float s[64][33];
    int z = blockIdx.y;                 // sb*4+g
    int sb = z >> 2, g = z & 3;
    int px0 = blockIdx.x * 32;
    int tid = threadIdx.x;
    int px = tid & 31, icq = tid >> 5;
    const float* src = g_bn + ((size_t)sb * C4C + g * 64) * HWp + px0;
    #pragma unroll
    for (int j = 0; j < 8; j++) {
        int ic = icq * 8 + j;
        s[ic][px] = src[(size_t)ic * HWp + px];
    }
    __syncthreads();
    int opx = tid >> 3, ic0 = (tid & 7) * 8;
    __nv_bfloat16 h[8], m[8];
    #pragma unroll
    for (int j = 0; j < 8; j++) split2(s[ic0 + j][opx], h[j], m[j]);
    size_t o = ((size_t)z * HWp + px0 + opx) * 64 + ic0;
    *(uint4*)(g_aH + o) = *(uint4*)h;
    *(uint4*)(g_aM + o) = *(uint4*)m;
}

// ---------------- prep: weights OIHW -> [g][khw][ocl][ic] bf16 2-term ----------------
__global__ void prep_weights_kernel(const float* __restrict__ w1, const float* __restrict__ w2) {
    int idx = blockIdx.x * blockDim.x + threadIdx.x;
    if (idx >= 4*9*64*64) return;
    int ic  = idx & 63;
    int ocl = (idx >> 6) & 63;
    int rest = idx >> 12;
    int g = rest / 9, khw = rest % 9;
    size_t si = ((size_t)(g*64 + ocl) * 64 + ic) * 9 + khw;
    __nv_bfloat16 h, m;
    split2(w1[si], h, m); g_w1H[idx] = h; g_w1M[idx] = m;
    split2(w2[si], h, m); g_w2H[idx] = h; g_w2M[idx] = m;
}

// ---------------- mma.sync grouped conv3x3 ----------------
// Tile: 128 px (4 rows x 32 cols) x 64 oc, k=64 per tap, 9 taps, passes hh+hm+mh.
// smem: A_h@0, A_m@18432, B_h@36864, B_m@46080 (pitch 72 bf16 = 144 B rows) = 55296 B
template<int STAGE>
__global__ __launch_bounds__(256)
void conv_mma_kernel(const float* __restrict__ bias) {
    extern __shared__ __align__(16) char smraw[];
    const int tid = threadIdx.x;
    const int warp = tid >> 5, lane = tid & 31;
    int z = blockIdx.z, sb = z >> 2, g = z & 3;
    int y0 = blockIdx.y * 4, x0 = blockIdx.x * 32;

    const __nv_bfloat16* A0 = (STAGE == 0) ? g_aH : g_yH;
    const __nv_bfloat16* A1 = (STAGE == 0) ? g_aM : g_yM;
    const __nv_bfloat16* B0 = (STAGE == 0) ? g_w1H : g_w2H;
    const __nv_bfloat16* B1 = (STAGE == 0) ? g_w1M : g_w2M;

    float acc[8][4];
    #pragma unroll
    for (int nb = 0; nb < 8; nb++)
        #pragma unroll
        for (int e = 0; e < 4; e++) acc[nb][e] = 0.f;

    uint32_t sbase = smem_u32(smraw);
    int m0 = warp * 16;
    // A ldmatrix per-lane address pieces
    uint32_t a_off = ((uint32_t)(m0 + (lane & 15)) * 72 + (lane >> 4) * 8) * 2;
    // B ldmatrix per-lane pieces
    uint32_t b_row = (lane & 7) + ((lane >> 1) & 8);
    uint32_t b_k   = ((lane >> 3) & 1) * 8;

    for (int tap = 0; tap < 9; tap++) {
        int dy = tap / 3 - 1, dx = tap % 3 - 1;
        __syncthreads();
        // stage A (both terms), boundary-checked
        for (int i = tid; i < 1024; i += 256) {
            int ar = i >> 3, seg = i & 7;
            int y = y0 + (ar >> 5) + dy, x = x0 + (ar & 31) + dx;
            uint4 vh = make_uint4(0,0,0,0), vm = make_uint4(0,0,0,0);
            if (y >= 0 && y < HH && x >= 0 && x < WW) {
                size_t si = ((size_t)z * HWp + (size_t)y * WW + x) * 8 + seg;
                vh = ((const uint4*)A0)[si];
                vm = ((const uint4*)A1)[si];
            }
            *(uint4*)(smraw +         ar * 144 + seg * 16) = vh;
            *(uint4*)(smraw + 18432 + ar * 144 + seg * 16) = vm;
        }
        // stage B (both terms)
        for (int i = tid; i < 512; i += 256) {
            int br = i >> 3, seg = i & 7;
            size_t si = (((size_t)g * 9 + tap) * 64 + br) * 8 + seg;
            *(uint4*)(smraw + 36864 + br * 144 + seg * 16) = ((const uint4*)B0)[si];
            *(uint4*)(smraw + 46080 + br * 144 + seg * 16) = ((const uint4*)B1)[si];
        }
        __syncthreads();

        #pragma unroll
        for (int k = 0; k < 4; k++) {        // k-chunk of 16 ic
            uint32_t ah[4], am[4];
            ldm_x4(ah, sbase +         a_off + k * 32);
            ldm_x4(am, sbase + 18432 + a_off + k * 32);
            #pragma unroll
            for (int nb2 = 0; nb2 < 4; nb2++) {
                uint32_t boff = ((nb2 * 16 + b_row) * 72 + k * 16 + b_k) * 2;
                uint32_t bh[4], bm[4];
                ldm_x4(bh, sbase + 36864 + boff);
                ldm_x4(bm, sbase + 46080 + boff);
                mma16816(acc[2*nb2    ], ah, bh[0], bh[1]);
                mma16816(acc[2*nb2    ], ah, bm[0], bm[1]);
                mma16816(acc[2*nb2    ], am, bh[0], bh[1]);
                mma16816(acc[2*nb2 + 1], ah, bh[2], bh[3]);
                mma16816(acc[2*nb2 + 1], ah, bm[2], bm[3]);
                mma16816(acc[2*nb2 + 1], am, bh[2], bh[3]);
            }
        }
    }

    int tq = lane >> 2, tr = lane & 3;
    __syncthreads();

    if (STAGE == 0) {
        float* stg = (float*)smraw;          // [128][65] = 33280 B
        #pragma unroll
        for (int nb = 0; nb < 8; nb++) {
            int col = nb * 8 + tr * 2;
            float b0 = bias[g * 64 + col], b1 = bias[g * 64 + col + 1];
            float v0 = acc[nb][0] + b0, v1 = acc[nb][1] + b1;
            float v2 = acc[nb][2] + b0, v3 = acc[nb][3] + b1;
            v0 = v0 > 0.f ? v0 : 0.1f * v0;
            v1 = v1 > 0.f ? v1 : 0.1f * v1;
            v2 = v2 > 0.f ? v2 : 0.1f * v2;
            v3 = v3 > 0.f ? v3 : 0.1f * v3;
            stg[(m0 + tq    ) * 65 + col    ] = v0;
            stg[(m0 + tq    ) * 65 + col + 1] = v1;
            stg[(m0 + 8 + tq) * 65 + col    ] = v2;
            stg[(m0 + 8 + tq) * 65 + col + 1] = v3;
        }
        __syncthreads();
        for (int i = tid; i < 1024; i += 256) {
            int ar = i >> 3, seg = i & 7;
            __nv_bfloat16 h[8], m[8];
            #pragma unroll
            for (int j = 0; j < 8; j++) split2(stg[ar * 65 + seg * 8 + j], h[j], m[j]);
            size_t o = ((size_t)z * HWp + (size_t)(y0 + (ar >> 5)) * WW + (x0 + (ar & 31))) * 8 + seg;
            ((uint4*)g_yH)[o] = *(uint4*)h;
            ((uint4*)g_yM)[o] = *(uint4*)m;
        }
    } else {
        float* stg = (float*)smraw;          // [64 oc][128 px] = 32768 B
        #pragma unroll
        for (int nb = 0; nb < 8; nb++) {
            int col = nb * 8 + tr * 2;
            float b0 = bias[g * 64 + col], b1 = bias[g * 64 + col + 1];
            stg[(col    ) * 128 + m0 + tq    ] = acc[nb][0] + b0;
            stg[(col + 1) * 128 + m0 + tq    ] = acc[nb][1] + b1;
            stg[(col    ) * 128 + m0 + 8 + tq] = acc[nb][2] + b0;
            stg[(col + 1) * 128 + m0 + 8 + tq] = acc[nb][3] + b1;
        }
        __syncthreads();
        for (int i = tid; i < 64 * 128; i += 256) {
            int oc = i >> 7, px = i & 127;
            size_t gi = ((size_t)sb * C4C + g * 64 + oc) * HWp
                      + (size_t)(y0 + (px >> 5)) * WW + (x0 + (px & 31));
            g_res[gi] = stg[oc * 128 + px] + g_bn[gi];
        }
    }
}

// ---------------- transposes ----------------
__global__ void transpose_in_kernel(const float* __restrict__ in, int which) {
    __shared__ float tile[32][33];
    float* out = which ? g_xr : g_xl;
    int b = blockIdx.z;
    const float* inb = in + (size_t)b * CC * HWp;
    float* outb      = out + (size_t)b * HWp * CC;
    int p0 = blockIdx.x * 32, c0 = blockIdx.y * 32;
    int tx = threadIdx.x, ty = threadIdx.y;
    #pragma unroll
    for (int i = 0; i < 32; i += 8)
        tile[ty + i][tx] = inb[(size_t)(c0 + ty + i) * HWp + p0 + tx];
    __syncthreads();
    #pragma unroll
    for (int i = 0; i < 32; i += 8)
        outb[(size_t)(p0 + ty + i) * CC + c0 + tx] = tile[tx][ty + i];
}
__global__ void transpose_out_kernel(float* __restrict__ outbase, int which) {
    __shared__ float tile[32][33];
    const float* in = which ? g_oR : g_oL;
    float* out = outbase + (size_t)which * NTOT;
    int b = blockIdx.z;
    const float* inb = in + (size_t)b * HWp * CC;
    float* outb      = out + (size_t)b * CC * HWp;
    int c0 = blockIdx.x * 32, p0 = blockIdx.y * 32;
    int tx = threadIdx.x, ty = threadIdx.y;
    #pragma unroll
    for (int i = 0; i < 32; i += 8)
        tile[ty + i][tx] = inb[(size_t)(p0 + ty + i) * CC + c0 + tx];
    __syncthreads();
    #pragma unroll
    for (int i = 0; i < 32; i += 8)
        outb[(size_t)(c0 + ty + i) * HWp + p0 + tx] = tile[tx][ty + i];
}

// ---------------- f32x2 helpers ----------------
__device__ __forceinline__ uint64_t pack2(float lo, float hi) {
    uint64_t r; asm("mov.b64 %0, {%1, %2};" : "=l"(r) : "f"(lo), "f"(hi)); return r;
}
__device__ __forceinline__ void unpack2(uint64_t v, float& lo, float& hi) {
    asm("mov.b64 {%0, %1}, %2;" : "=f"(lo), "=f"(hi) : "l"(v));
}
__device__ __forceinline__ void ffma2(uint64_t& d, uint64_t a, uint64_t b) {
    asm("fma.rn.f32x2 %0, %1, %2, %0;" : "+l"(d) : "l"(a), "l"(b));
}

// ---------------- grouped 1x1 conv -> Q/K NHWC ----------------
__global__ __launch_bounds__(256)
void conv1x1_kernel(const float* __restrict__ bq_w, const float* __restrict__ bq_b,
                    const float* __restrict__ bs_w, const float* __restrict__ bs_b) {
    __shared__ float in_s[64][64];
    __shared__ float w_sh[16][64];
    int side = blockIdx.z, g = blockIdx.y;
    int p0 = blockIdx.x * 64;
    int b = p0 / HWp;
    int tid = threadIdx.x;
    const float* wsrc = side ? bs_w : bq_w;
    const float* bsrc = side ? bs_b : bq_b;
    for (int i = tid; i < 16*64; i += 256) {
        int oc = i >> 6, ic = i & 63;
        w_sh[oc][ic] = wsrc[(g*16 + oc)*64 + ic];
    }
    const float* resb = g_res + ((size_t)(side*BB + b) * C4C + g*64) * HWp + (p0 - b*HWp);
    for (int i = tid; i < 64*64; i += 256) {
        int ch = i >> 6, px = i & 63;
        in_s[ch][px] = resb[(size_t)ch * HWp + px];
    }
    __syncthreads();
    int oc = tid & 15, pq = tid >> 4;
    uint64_t acc[2] = {0ull, 0ull};
    #pragma unroll 8
    for (int ic = 0; ic < 64; ic++) {
        float wv = w_sh[oc][ic];
        uint64_t ww = pack2(wv, wv);
        const uint64_t* irow = (const uint64_t*)&in_s[ic][pq*4];
        ffma2(acc[0], irow[0], ww);
        ffma2(acc[1], irow[1], ww);
    }
    float bv = bsrc[g*16 + oc];
    float* o = side ? g_K : g_Q;
    int ocg = g*16 + oc;
    #pragma unroll
    for (int j = 0; j < 2; j++) {
        float lo, hi;
        unpack2(acc[j], lo, hi);
        int px = pq*4 + 2*j;
        o[(size_t)(p0 + px    ) * CC + ocg] = lo + bv;
        o[(size_t)(p0 + px + 1) * CC + ocg] = hi + bv;
    }
}

// ---------------- reductions ----------------
__device__ __forceinline__ float block2_max(float v, volatile float* red, int t) {
    #pragma unroll
    for (int o = 16; o; o >>= 1) v = fmaxf(v, __shfl_xor_sync(0xffffffffu, v, o));
    if ((t & 31) == 0) red[t >> 5] = v;
    __syncthreads();
    float r = fmaxf(red[0], red[1]);
    __syncthreads();
    return r;
}
__device__ __forceinline__ float block2_sum(float v, volatile float* red, int t) {
    #pragma unroll
    for (int o = 16; o; o >>= 1) v += __shfl_xor_sync(0xffffffffu, v, o);
    if ((t & 31) == 0) red[t >> 5] = v;
    __syncthreads();
    float r = red[0] + red[1];
    __syncthreads();
    return r;
}

// ---------------- attention ----------------
__global__ __launch_bounds__(64)
void attn_kernel(const int* __restrict__ d_left, const int* __restrict__ d_right) {
    __shared__ __align__(16) float q_s[64];
    __shared__ __align__(16) float k_s[64];
    __shared__ float s1_s[64], s2_s[64];
    __shared__ int   cd_s[64];
    __shared__ float red[2];

    int pix = blockIdx.x;
    int b  = pix / HWp;
    int hp = pix % HWp;
    int h  = hp / WW, w = hp % WW;
    int t  = threadIdx.x;

    q_s[t] = g_Q[(size_t)pix * CC + t];
    k_s[t] = g_K[(size_t)pix * CC + t];

    int dl = d_left[pix], dr = d_right[pix];
    int c1 = max(w - dl, 0);
    int c2 = min(w + dr, WW - 1);
    bool rowok  = (h < HH - PP);
    bool valid1 = rowok && (c1 < WW - PP);
    bool valid2 = rowok && (c2 < WW - PP);
    __syncthreads();

    int a = t >> 3, bb2 = t & 7;
    int y  = h + a - PP;
    int x1 = c1 + bb2 - PP;
    int x2 = c2 + bb2 - PP;
    bool in1 = valid1 && (y >= 0) && (y < HH) && (x1 >= 0) && (x1 < WW);
    bool in2 = valid2 && (y >= 0) && (y < HH) && (x2 >= 0) && (x2 < WW);

    float r1 = 0.f, r2 = 0.f;
    if (in1) {
        const float4* kr = (const float4*)(g_K + ((size_t)b*HWp + (size_t)y*WW + x1) * CC);
        const float4* qv = (const float4*)q_s;
        #pragma unroll
        for (int i = 0; i < 16; i++) {
            float4 kv = kr[i]; float4 q4 = qv[i];
            r1 += q4.x*kv.x + q4.y*kv.y + q4.z*kv.z + q4.w*kv.w;
        }
    }
    if (in2) {
        const float4* qr = (const float4*)(g_Q + ((size_t)b*HWp + (size_t)y*WW + x2) * CC);
        const float4* k4v = (const float4*)k_s;
        #pragma unroll
        for (int i = 0; i < 16; i++) {
            float4 qv2 = qr[i]; float4 k4 = k4v[i];
            r2 += k4.x*qv2.x + k4.y*qv2.y + k4.z*qv2.z + k4.w*qv2.w;
        }
    }
    cd_s[t] = in1 ? (y * WW + x1) : -1;

    float m1 = block2_max(r1, red, t);
    float e1 = __expf(r1 - m1);
    float z1 = block2_sum(e1, red, t);
    float m2 = block2_max(r2, red, t);
    float e2 = __expf(r2 - m2);
    float z2 = block2_sum(e2, red, t);
    s1_s[t] = e1 / z1;
    s2_s[t] = e2 / z2;
    __syncthreads();

    const float* xrb = g_xr + (size_t)b * HWp * CC;
    const float* xlb = g_xl + (size_t)b * HWp * CC;
    float accL = 0.f, accR = 0.f;
    #pragma unroll 4
    for (int k = 0; k < 64; k++) {
        int cd = cd_s[k];
        if (cd >= 0) {
            accL = fmaf(s1_s[k], xrb[(size_t)cd * CC + t], accL);
            accR = fmaf(s2_s[k], xlb[(size_t)cd * CC + t], accR);
        }
    }
    float VL = (w - dl >= 0)    ? 1.f : 0.f;
    float VR = (w + dr <= WW-1) ? 1.f : 0.f;
    size_t oi = (size_t)pix * CC + t;
    g_oL[oi] = xlb[(size_t)hp * CC + t] + VL * accL;
    g_oR[oi] = xrb[(size_t)hp * CC + t] + VR * accR;
}

// ---------------- launch ----------------
#define CONV_SMEM 55296

extern "C" void kernel_launch(void* const* d_in, const int* in_sizes, int n_in,
                              void* d_out, int out_size) {
    (void)n_in; (void)out_size;
    const float *xl, *xr, *cl, *cr, *bg, *bbeta, *bm, *bv;
    const float *w1, *b1, *w2, *b2, *bqw, *bqb, *bsw, *bsb;
    const int *dl, *dr;

    if (in_sizes[4] == BB*HH*WW) {
        xl  = (const float*)d_in[0];  xr  = (const float*)d_in[1];
        cl  = (const float*)d_in[2];  cr  = (const float*)d_in[3];
        dl  = (const int*)  d_in[4];  dr  = (const int*)  d_in[5];
        bg  = (const float*)d_in[6];  bbeta=(const float*)d_in[7];
        bm  = (const float*)d_in[8];  bv  = (const float*)d_in[9];
        w1  = (const float*)d_in[10]; b1  = (const float*)d_in[11];
        w2  = (const float*)d_in[12]; b2  = (const float*)d_in[13];
        bqw = (const float*)d_in[14]; bqb = (const float*)d_in[15];
        bsw = (const float*)d_in[16]; bsb = (const float*)d_in[17];
    } else {
        xl  = (const float*)d_in[0];  xr  = (const float*)d_in[1];
        cl  = (const float*)d_in[2];  cr  = (const float*)d_in[3];
        bg  = (const float*)d_in[4];  bbeta=(const float*)d_in[5];
        bm  = (const float*)d_in[6];  bv  = (const float*)d_in[7];
        w1  = (const float*)d_in[8];  b1  = (const float*)d_in[9];
        w2  = (const float*)d_in[10]; b2  = (const float*)d_in[11];
        bqw = (const float*)d_in[12]; bqb = (const float*)d_in[13];
        bsw = (const float*)d_in[14]; bsb = (const float*)d_in[15];
        dl  = (const int*)  d_in[16]; dr  = (const int*)  d_in[17];
    }

    cudaFuncSetAttribute(conv_mma_kernel<0>, cudaFuncAttributeMaxDynamicSharedMemorySize, CONV_SMEM);
    cudaFuncSetAttribute(conv_mma_kernel<1>, cudaFuncAttributeMaxDynamicSharedMemorySize, CONV_SMEM);

    dim3 tb(32, 8);
    dim3 cgrid(WW/32, HH/4, SBG);   // (3, 16, 16)

    bn_kernel<<<(BB*C4C*HWp + 255)/256, 256>>>(cl, cr, bg, bbeta, bm, bv);
    prep_input_kernel<<<dim3(HWp/32, SBG), 256>>>();
    prep_weights_kernel<<<(4*9*64*64 + 255)/256, 256>>>(w1, w2);
    transpose_in_kernel<<<dim3(HWp/32, CC/32, BB), tb>>>(xl, 0);
    transpose_in_kernel<<<dim3(HWp/32, CC/32, BB), tb>>>(xr, 1);

    conv_mma_kernel<0><<<cgrid, 256, CONV_SMEM>>>(b1);
    conv_mma_kernel<1><<<cgrid, 256, CONV_SMEM>>>(b2);

    conv1x1_kernel<<<dim3(BB*HWp/64, 4, 2), 256>>>(bqw, bqb, bsw, bsb);
    attn_kernel<<<NPIX, 64>>>(dl, dr);

    transpose_out_kernel<<<dim3(CC/32, HWp/32, BB), tb>>>((float*)d_out, 0);
    transpose_out_kernel<<<dim3(CC/32, HWp/32, BB), tb>>>((float*)d_out, 1);
}

// round 8
// speedup vs baseline: 2.2216x; 1.0497x over previous
#include <cuda_runtime.h>
#include <cuda_bf16.h>
#include <math.h>
#include <stdint.h>

#define BB 2
#define CC 64
#define HH 64
#define WW 96
#define C4C 256
#define HWp (HH*WW)
#define NPIX (BB*HH*WW)
#define NTOT (BB*CC*HH*WW)
#define PP 4
#define SBG 16

// ---------------- scratch ----------------
__device__ float g_bn [SBG*64*HWp];
__device__ float g_res[SBG*64*HWp];
__device__ __align__(16) __nv_bfloat16 g_aH[SBG*HWp*64], g_aM[SBG*HWp*64];
__device__ __align__(16) __nv_bfloat16 g_yH[SBG*HWp*64], g_yM[SBG*HWp*64];
__device__ __align__(16) __nv_bfloat16 g_w1H[4*9*64*64], g_w1M[4*9*64*64];
__device__ __align__(16) __nv_bfloat16 g_w2H[4*9*64*64], g_w2M[4*9*64*64];
__device__ float g_Q[NTOT], g_K[NTOT], g_xl[NTOT], g_xr[NTOT], g_oL[NTOT], g_oR[NTOT];

__device__ __forceinline__ uint32_t smem_u32(const void* p) {
    uint32_t a;
    asm("{ .reg .u64 t; cvta.to.shared.u64 t, %1; cvt.u32.u64 %0, t; }" : "=r"(a) : "l"(p));
    return a;
}
__device__ __forceinline__ void ldm_x4(uint32_t* r, uint32_t addr) {
    asm volatile("ldmatrix.sync.aligned.m8n8.x4.shared.b16 {%0,%1,%2,%3}, [%4];"
        : "=r"(r[0]), "=r"(r[1]), "=r"(r[2]), "=r"(r[3]) : "r"(addr));
}
__device__ __forceinline__ void mma16816(float* d, const uint32_t* a, uint32_t b0, uint32_t b1) {
    asm volatile("mma.sync.aligned.m16n8k16.row.col.f32.bf16.bf16.f32 "
        "{%0,%1,%2,%3}, {%4,%5,%6,%7}, {%8,%9}, {%0,%1,%2,%3};"
        : "+f"(d[0]), "+f"(d[1]), "+f"(d[2]), "+f"(d[3])
        : "r"(a[0]), "r"(a[1]), "r"(a[2]), "r"(a[3]), "r"(b0), "r"(b1));
}
__device__ __forceinline__ void cp16(uint32_t dst, const void* src, bool pred) {
    asm volatile("cp.async.cg.shared.global [%0], [%1], 16, %2;"
        :: "r"(dst), "l"(src), "r"(pred ? 16 : 0) : "memory");
}
#define CP_COMMIT() asm volatile("cp.async.commit_group;" ::: "memory")
#define CP_WAIT0()  asm volatile("cp.async.wait_group 0;" ::: "memory")

__device__ __forceinline__ void split2(float x, __nv_bfloat16& h, __nv_bfloat16& m) {
    h = __float2bfloat16_rn(x);
    m = __float2bfloat16_rn(x - __bfloat162float(h));
}

// ---------------- fused BN + bf16 split (NCHW -> g_bn NCHW + g_aH/M NGHWC) ----------------
__global__ __launch_bounds__(256)
void bn_prep_kernel(const float* __restrict__ cl, const float* __restrict__ cr,
                    const float* __restrict__ gg, const float* __restrict__ bt,
                    const float* __restrict__ mn, const float* __restrict__ vr) {
    __shared__ float s[64][33];
    int z = blockIdx.y;                 // sb*4+g ; sb = side*2+b
    int sb = z >> 2, g = z & 3;
    int side = sb >> 1, b = sb & 1;
    int px0 = blockIdx.x * 32;
    int tid = threadIdx.x;
    int px = tid & 31, icq = tid >> 5;
    const float* src = (side ? cr : cl) + ((size_t)b * C4C + g * 64) * HWp + px0;
    float* bdst = g_bn + ((size_t)sb * C4C + g * 64) * HWp + px0;
    #pragma unroll
    for (int j = 0; j < 8; j++) {
        int ic = icq * 8 + j;
        int ch = g * 64 + ic;
        float sc = gg[ch] * rsqrtf(vr[ch] + 1e-5f);
        float sh = bt[ch] - mn[ch] * sc;
        float v = fmaf(src[(size_t)ic * HWp + px], sc, sh);
        s[ic][px] = v;
        bdst[(size_t)ic * HWp + px] = v;
    }
    __syncthreads();
    int opx = tid >> 3, ic0 = (tid & 7) * 8;
    __nv_bfloat16 h[8], m[8];
    #pragma unroll
    for (int j = 0; j < 8; j++) split2(s[ic0 + j][opx], h[j], m[j]);
    size_t o = ((size_t)z * HWp + px0 + opx) * 64 + ic0;
    *(uint4*)(g_aH + o) = *(uint4*)h;
    *(uint4*)(g_aM + o) = *(uint4*)m;
}

// ---------------- prep: weights OIHW -> [g][khw][ocl][ic] bf16 2-term ----------------
__global__ void prep_weights_kernel(const float* __restrict__ w1, const float* __restrict__ w2) {
    int idx = blockIdx.x * blockDim.x + threadIdx.x;
    if (idx >= 4*9*64*64) return;
    int ic  = idx & 63;
    int ocl = (idx >> 6) & 63;
    int rest = idx >> 12;
    int g = rest / 9, khw = rest % 9;
    size_t si = ((size_t)(g*64 + ocl) * 64 + ic) * 9 + khw;
    __nv_bfloat16 h, m;
    split2(w1[si], h, m); g_w1H[idx] = h; g_w1M[idx] = m;
    split2(w2[si], h, m); g_w2H[idx] = h; g_w2M[idx] = m;
}

// ---------------- mma.sync grouped conv3x3, halo-A + double-buffered B ----------------
// A halo: 6x34 px x 64 ch, pitch 144 B, 2 terms: A_h@0, A_m@29376 (58752 B)
// B:      2 bufs x (2 terms x 64 x 144) @ 58752 (36864 B).  Total 95616 B.
#define A_TERM  29376
#define B_BASE  58752
#define B_BUF   18432
#define B_TERM  9216
#define CONV_SMEM 95616

template<int STAGE>
__global__ __launch_bounds__(256, 2)
void conv_mma_kernel(const float* __restrict__ bias) {
    extern __shared__ __align__(16) char smraw[];
    const int tid = threadIdx.x;
    const int warp = tid >> 5, lane = tid & 31;
    int z = blockIdx.z, sb = z >> 2, g = z & 3;
    int y0 = blockIdx.y * 4, x0 = blockIdx.x * 32;

    const __nv_bfloat16* A0 = (STAGE == 0) ? g_aH : g_yH;
    const __nv_bfloat16* A1 = (STAGE == 0) ? g_aM : g_yM;
    const __nv_bfloat16* B0 = (STAGE == 0) ? g_w1H : g_w2H;
    const __nv_bfloat16* B1 = (STAGE == 0) ? g_w1M : g_w2M;

    uint32_t sbase = smem_u32(smraw);

    // ---- stage A halo (both terms) + B tap0 via cp.async ----
    for (int i = tid; i < 204 * 8; i += 256) {
        int hr = i >> 3, seg = i & 7;
        int hy = hr / 34, hx = hr % 34;
        int y = y0 - 1 + hy, x = x0 - 1 + hx;
        bool ok = (y >= 0) && (y < HH) && (x >= 0) && (x < WW);
        size_t si = ((size_t)z * HWp + (size_t)y * WW + x) * 8 + seg;
        uint32_t dst = sbase + hr * 144 + seg * 16;
        cp16(dst,          (const uint4*)A0 + (ok ? si : 0), ok);
        cp16(dst + A_TERM, (const uint4*)A1 + (ok ? si : 0), ok);
    }
    for (int i = tid; i < 512; i += 256) {
        int br = i >> 3, seg = i & 7;
        size_t si = (((size_t)g * 9 + 0) * 64 + br) * 8 + seg;
        uint32_t dst = sbase + B_BASE + br * 144 + seg * 16;
        cp16(dst,          (const uint4*)B0 + si, true);
        cp16(dst + B_TERM, (const uint4*)B1 + si, true);
    }
    CP_COMMIT();

    float acc[8][4];
    #pragma unroll
    for (int nb = 0; nb < 8; nb++)
        #pragma unroll
        for (int e = 0; e < 4; e++) acc[nb][e] = 0.f;

    int m0 = warp * 16;
    int pxr = (m0 + (lane & 15)) >> 5;        // 0..3 (px row within 4-row tile)
    int pxc = (m0 + (lane & 15)) & 31;        // 0..31
    uint32_t a_half = (lane >> 4) * 16;       // k-half byte offset
    uint32_t b_row = (lane & 7) + ((lane >> 1) & 8);
    uint32_t b_k   = ((lane >> 3) & 1) * 8;

    CP_WAIT0();
    __syncthreads();

    int buf = 0;
    #pragma unroll 1
    for (int tap = 0; tap < 9; tap++) {
        // prefetch next tap's B into the other buffer
        if (tap < 8) {
            int nb = buf ^ 1;
            for (int i = tid; i < 512; i += 256) {
                int br = i >> 3, seg = i & 7;
                size_t si = (((size_t)g * 9 + tap + 1) * 64 + br) * 8 + seg;
                uint32_t dst = sbase + B_BASE + nb * B_BUF + br * 144 + seg * 16;
                cp16(dst,          (const uint4*)B0 + si, true);
                cp16(dst + B_TERM, (const uint4*)B1 + si, true);
            }
            CP_COMMIT();
        }

        // per-lane A address for this tap (halo coords)
        int hy = pxr + tap / 3;               // dy+1
        int hx = pxc + tap % 3;               // dx+1
        uint32_t a_addr = sbase + (uint32_t)(hy * 34 + hx) * 144 + a_half;
        uint32_t bb = sbase + B_BASE + buf * B_BUF;

        #pragma unroll
        for (int k = 0; k < 4; k++) {
            uint32_t ah[4], am[4];
            ldm_x4(ah, a_addr          + k * 32);
            ldm_x4(am, a_addr + A_TERM + k * 32);
            #pragma unroll
            for (int nb2 = 0; nb2 < 4; nb2++) {
                uint32_t boff = ((nb2 * 16 + b_row) * 144) + (k * 16 + b_k) * 2;
                uint32_t bh[4], bm[4];
                ldm_x4(bh, bb + boff);
                ldm_x4(bm, bb + B_TERM + boff);
                mma16816(acc[2*nb2    ], ah, bh[0], bh[1]);
                mma16816(acc[2*nb2    ], ah, bm[0], bm[1]);
                mma16816(acc[2*nb2    ], am, bh[0], bh[1]);
                mma16816(acc[2*nb2 + 1], ah, bh[2], bh[3]);
                mma16816(acc[2*nb2 + 1], ah, bm[2], bm[3]);
                mma16816(acc[2*nb2 + 1], am, bh[2], bh[3]);
            }
        }

        if (tap < 8) {
            CP_WAIT0();
            __syncthreads();
            buf ^= 1;
        }
    }

    int tq = lane >> 2, tr = lane & 3;
    __syncthreads();

    if (STAGE == 0) {
        float* stg = (float*)smraw;          // [128][65]
        #pragma unroll
        for (int nb = 0; nb < 8; nb++) {
            int col = nb * 8 + tr * 2;
            float b0 = bias[g * 64 + col], b1 = bias[g * 64 + col + 1];
            float v0 = acc[nb][0] + b0, v1 = acc[nb][1] + b1;
            float v2 = acc[nb][2] + b0, v3 = acc[nb][3] + b1;
            v0 = v0 > 0.f ? v0 : 0.1f * v0;
            v1 = v1 > 0.f ? v1 : 0.1f * v1;
            v2 = v2 > 0.f ? v2 : 0.1f * v2;
            v3 = v3 > 0.f ? v3 : 0.1f * v3;
            stg[(m0 + tq    ) * 65 + col    ] = v0;
            stg[(m0 + tq    ) * 65 + col + 1] = v1;
            stg[(m0 + 8 + tq) * 65 + col    ] = v2;
            stg[(m0 + 8 + tq) * 65 + col + 1] = v3;
        }
        __syncthreads();
        for (int i = tid; i < 1024; i += 256) {
            int ar = i >> 3, seg = i & 7;
            __nv_bfloat16 h[8], m[8];
            #pragma unroll
            for (int j = 0; j < 8; j++) split2(stg[ar * 65 + seg * 8 + j], h[j], m[j]);
            size_t o = ((size_t)z * HWp + (size_t)(y0 + (ar >> 5)) * WW + (x0 + (ar & 31))) * 8 + seg;
            ((uint4*)g_yH)[o] = *(uint4*)h;
            ((uint4*)g_yM)[o] = *(uint4*)m;
        }
    } else {
        float* stg = (float*)smraw;          // [64 oc][128 px]
        #pragma unroll
        for (int nb = 0; nb < 8; nb++) {
            int col = nb * 8 + tr * 2;
            float b0 = bias[g * 64 + col], b1 = bias[g * 64 + col + 1];
            stg[(col    ) * 128 + m0 + tq    ] = acc[nb][0] + b0;
            stg[(col + 1) * 128 + m0 + tq    ] = acc[nb][1] + b1;
            stg[(col    ) * 128 + m0 + 8 + tq] = acc[nb][2] + b0;
            stg[(col + 1) * 128 + m0 + 8 + tq] = acc[nb][3] + b1;
        }
        __syncthreads();
        for (int i = tid; i < 64 * 128; i += 256) {
            int oc = i >> 7, px = i & 127;
            size_t gi = ((size_t)sb * C4C + g * 64 + oc) * HWp
                      + (size_t)(y0 + (px >> 5)) * WW + (x0 + (px & 31));
            g_res[gi] = stg[oc * 128 + px] + g_bn[gi];
        }
    }
}

// ---------------- transposes ----------------
__global__ void transpose_in_kernel(const float* __restrict__ in, int which) {
    __shared__ float tile[32][33];
    float* out = which ? g_xr : g_xl;
    int b = blockIdx.z;
    const float* inb = in + (size_t)b * CC * HWp;
    float* outb      = out + (size_t)b * HWp * CC;
    int p0 = blockIdx.x * 32, c0 = blockIdx.y * 32;
    int tx = threadIdx.x, ty = threadIdx.y;
    #pragma unroll
    for (int i = 0; i < 32; i += 8)
        tile[ty + i][tx] = inb[(size_t)(c0 + ty + i) * HWp + p0 + tx];
    __syncthreads();
    #pragma unroll
    for (int i = 0; i < 32; i += 8)
        outb[(size_t)(p0 + ty + i) * CC + c0 + tx] = tile[tx][ty + i];
}
__global__ void transpose_out_kernel(float* __restrict__ outbase, int which) {
    __shared__ float tile[32][33];
    const float* in = which ? g_oR : g_oL;
    float* out = outbase + (size_t)which * NTOT;
    int b = blockIdx.z;
    const float* inb = in + (size_t)b * HWp * CC;
    float* outb      = out + (size_t)b * CC * HWp;
    int c0 = blockIdx.x * 32, p0 = blockIdx.y * 32;
    int tx = threadIdx.x, ty = threadIdx.y;
    #pragma unroll
    for (int i = 0; i < 32; i += 8)
        tile[ty + i][tx] = inb[(size_t)(p0 + ty + i) * CC + c0 + tx];
    __syncthreads();
    #pragma unroll
    for (int i = 0; i < 32; i += 8)
        outb[(size_t)(c0 + ty + i) * HWp + p0 + tx] = tile[tx][ty + i];
}

// ---------------- f32x2 helpers ----------------
__device__ __forceinline__ uint64_t pack2(float lo, float hi) {
    uint64_t r; asm("mov.b64 %0, {%1, %2};" : "=l"(r) : "f"(lo), "f"(hi)); return r;
}
__device__ __forceinline__ void unpack2(uint64_t v, float& lo, float& hi) {
    asm("mov.b64 {%0, %1}, %2;" : "=f"(lo), "=f"(hi) : "l"(v));
}
__device__ __forceinline__ void ffma2(uint64_t& d, uint64_t a, uint64_t b) {
    asm("fma.rn.f32x2 %0, %1, %2, %0;" : "+l"(d) : "l"(a), "l"(b));
}

// ---------------- grouped 1x1 conv -> Q/K NHWC ----------------
__global__ __launch_bounds__(256)
void conv1x1_kernel(const float* __restrict__ bq_w, const float* __restrict__ bq_b,
                    const float* __restrict__ bs_w, const float* __restrict__ bs_b) {
    __shared__ float in_s[64][64];
    __shared__ float w_sh[16][64];
    int side = blockIdx.z, g = blockIdx.y;
    int p0 = blockIdx.x * 64;
    int b = p0 / HWp;
    int tid = threadIdx.x;
    const float* wsrc = side ? bs_w : bq_w;
    const float* bsrc = side ? bs_b : bq_b;
    for (int i = tid; i < 16*64; i += 256) {
        int oc = i >> 6, ic = i & 63;
        w_sh[oc][ic] = wsrc[(g*16 + oc)*64 + ic];
    }
    const float* resb = g_res + ((size_t)(side*BB + b) * C4C + g*64) * HWp + (p0 - b*HWp);
    for (int i = tid; i < 64*64; i += 256) {
        int ch = i >> 6, px = i & 63;
        in_s[ch][px] = resb[(size_t)ch * HWp + px];
    }
    __syncthreads();
    int oc = tid & 15, pq = tid >> 4;
    uint64_t acc[2] = {0ull, 0ull};
    #pragma unroll 8
    for (int ic = 0; ic < 64; ic++) {
        float wv = w_sh[oc][ic];
        uint64_t ww = pack2(wv, wv);
        const uint64_t* irow = (const uint64_t*)&in_s[ic][pq*4];
        ffma2(acc[0], irow[0], ww);
        ffma2(acc[1], irow[1], ww);
    }
    float bv = bsrc[g*16 + oc];
    float* o = side ? g_K : g_Q;
    int ocg = g*16 + oc;
    #pragma unroll
    for (int j = 0; j < 2; j++) {
        float lo, hi;
        unpack2(acc[j], lo, hi);
        int px = pq*4 + 2*j;
        o[(size_t)(p0 + px    ) * CC + ocg] = lo + bv;
        o[(size_t)(p0 + px + 1) * CC + ocg] = hi + bv;
    }
}

// ---------------- reductions ----------------
__device__ __forceinline__ float block2_max(float v, volatile float* red, int t) {
    #pragma unroll
    for (int o = 16; o; o >>= 1) v = fmaxf(v, __shfl_xor_sync(0xffffffffu, v, o));
    if ((t & 31) == 0) red[t >> 5] = v;
    __syncthreads();
    float r = fmaxf(red[0], red[1]);
    __syncthreads();
    return r;
}
__device__ __forceinline__ float block2_sum(float v, volatile float* red, int t) {
    #pragma unroll
    for (int o = 16; o; o >>= 1) v += __shfl_xor_sync(0xffffffffu, v, o);
    if ((t & 31) == 0) red[t >> 5] = v;
    __syncthreads();
    float r = red[0] + red[1];
    __syncthreads();
    return r;
}

// ---------------- attention ----------------
__global__ __launch_bounds__(64)
void attn_kernel(const int* __restrict__ d_left, const int* __restrict__ d_right) {
    __shared__ __align__(16) float q_s[64];
    __shared__ __align__(16) float k_s[64];
    __shared__ float s1_s[64], s2_s[64];
    __shared__ int   cd_s[64];
    __shared__ float red[2];

    int pix = blockIdx.x;
    int b  = pix / HWp;
    int hp = pix % HWp;
    int h  = hp / WW, w = hp % WW;
    int t  = threadIdx.x;

    q_s[t] = g_Q[(size_t)pix * CC + t];
    k_s[t] = g_K[(size_t)pix * CC + t];

    int dl = d_left[pix], dr = d_right[pix];
    int c1 = max(w - dl, 0);
    int c2 = min(w + dr, WW - 1);
    bool rowok  = (h < HH - PP);
    bool valid1 = rowok && (c1 < WW - PP);
    bool valid2 = rowok && (c2 < WW - PP);
    __syncthreads();

    int a = t >> 3, bb2 = t & 7;
    int y  = h + a - PP;
    int x1 = c1 + bb2 - PP;
    int x2 = c2 + bb2 - PP;
    bool in1 = valid1 && (y >= 0) && (y < HH) && (x1 >= 0) && (x1 < WW);
    bool in2 = valid2 && (y >= 0) && (y < HH) && (x2 >= 0) && (x2 < WW);

    float r1 = 0.f, r2 = 0.f;
    if (in1) {
        const float4* kr = (const float4*)(g_K + ((size_t)b*HWp + (size_t)y*WW + x1) * CC);
        const float4* qv = (const float4*)q_s;
        #pragma unroll
        for (int i = 0; i < 16; i++) {
            float4 kv = kr[i]; float4 q4 = qv[i];
            r1 += q4.x*kv.x + q4.y*kv.y + q4.z*kv.z + q4.w*kv.w;
        }
    }
    if (in2) {
        const float4* qr = (const float4*)(g_Q + ((size_t)b*HWp + (size_t)y*WW + x2) * CC);
        const float4* k4v = (const float4*)k_s;
        #pragma unroll
        for (int i = 0; i < 16; i++) {
            float4 qv2 = qr[i]; float4 k4 = k4v[i];
            r2 += k4.x*qv2.x + k4.y*qv2.y + k4.z*qv2.z + k4.w*qv2.w;
        }
    }
    cd_s[t] = in1 ? (y * WW + x1) : -1;

    float m1 = block2_max(r1, red, t);
    float e1 = __expf(r1 - m1);
    float z1 = block2_sum(e1, red, t);
    float m2 = block2_max(r2, red, t);
    float e2 = __expf(r2 - m2);
    float z2 = block2_sum(e2, red, t);
    s1_s[t] = e1 / z1;
    s2_s[t] = e2 / z2;
    __syncthreads();

    const float* xrb = g_xr + (size_t)b * HWp * CC;
    const float* xlb = g_xl + (size_t)b * HWp * CC;
    float accL = 0.f, accR = 0.f;
    #pragma unroll 4
    for (int k = 0; k < 64; k++) {
        int cd = cd_s[k];
        if (cd >= 0) {
            accL = fmaf(s1_s[k], xrb[(size_t)cd * CC + t], accL);
            accR = fmaf(s2_s[k], xlb[(size_t)cd * CC + t], accR);
        }
    }
    float VL = (w - dl >= 0)    ? 1.f : 0.f;
    float VR = (w + dr <= WW-1) ? 1.f : 0.f;
    size_t oi = (size_t)pix * CC + t;
    g_oL[oi] = xlb[(size_t)hp * CC + t] + VL * accL;
    g_oR[oi] = xrb[(size_t)hp * CC + t] + VR * accR;
}

// ---------------- launch ----------------
extern "C" void kernel_launch(void* const* d_in, const int* in_sizes, int n_in,
                              void* d_out, int out_size) {
    (void)n_in; (void)out_size;
    const float *xl, *xr, *cl, *cr, *bg, *bbeta, *bm, *bv;
    const float *w1, *b1, *w2, *b2, *bqw, *bqb, *bsw, *bsb;
    const int *dl, *dr;

    if (in_sizes[4] == BB*HH*WW) {
        xl  = (const float*)d_in[0];  xr  = (const float*)d_in[1];
        cl  = (const float*)d_in[2];  cr  = (const float*)d_in[3];
        dl  = (const int*)  d_in[4];  dr  = (const int*)  d_in[5];
        bg  = (const float*)d_in[6];  bbeta=(const float*)d_in[7];
        bm  = (const float*)d_in[8];  bv  = (const float*)d_in[9];
        w1  = (const float*)d_in[10]; b1  = (const float*)d_in[11];
        w2  = (const float*)d_in[12]; b2  = (const float*)d_in[13];
        bqw = (const float*)d_in[14]; bqb = (const float*)d_in[15];
        bsw = (const float*)d_in[16]; bsb = (const float*)d_in[17];
    } else {
        xl  = (const float*)d_in[0];  xr  = (const float*)d_in[1];
        cl  = (const float*)d_in[2];  cr  = (const float*)d_in[3];
        bg  = (const float*)d_in[4];  bbeta=(const float*)d_in[5];
        bm  = (const float*)d_in[6];  bv  = (const float*)d_in[7];
        w1  = (const float*)d_in[8];  b1  = (const float*)d_in[9];
        w2  = (const float*)d_in[10]; b2  = (const float*)d_in[11];
        bqw = (const float*)d_in[12]; bqb = (const float*)d_in[13];
        bsw = (const float*)d_in[14]; bsb = (const float*)d_in[15];
        dl  = (const int*)  d_in[16]; dr  = (const int*)  d_in[17];
    }

    cudaFuncSetAttribute(conv_mma_kernel<0>, cudaFuncAttributeMaxDynamicSharedMemorySize, CONV_SMEM);
    cudaFuncSetAttribute(conv_mma_kernel<1>, cudaFuncAttributeMaxDynamicSharedMemorySize, CONV_SMEM);

    dim3 tb(32, 8);
    dim3 cgrid(WW/32, HH/4, SBG);   // (3, 16, 16)

    bn_prep_kernel<<<dim3(HWp/32, SBG), 256>>>(cl, cr, bg, bbeta, bm, bv);
    prep_weights_kernel<<<(4*9*64*64 + 255)/256, 256>>>(w1, w2);
    transpose_in_kernel<<<dim3(HWp/32, CC/32, BB), tb>>>(xl, 0);
    transpose_in_kernel<<<dim3(HWp/32, CC/32, BB), tb>>>(xr, 1);

    conv_mma_kernel<0><<<cgrid, 256, CONV_SMEM>>>(b1);
    conv_mma_kernel<1><<<cgrid, 256, CONV_SMEM>>>(b2);

    conv1x1_kernel<<<dim3(BB*HWp/64, 4, 2), 256>>>(bqw, bqb, bsw, bsb);
    attn_kernel<<<NPIX, 64>>>(dl, dr);

    transpose_out_kernel<<<dim3(CC/32, HWp/32, BB), tb>>>((float*)d_out, 0);
    transpose_out_kernel<<<dim3(CC/32, HWp/32, BB), tb>>>((float*)d_out, 1);
}

// round 9
// speedup vs baseline: 2.2487x; 1.0122x over previous
#include <cuda_runtime.h>
#include <cuda_bf16.h>
#include <math.h>
#include <stdint.h>

#define BB 2
#define CC 64
#define HH 64
#define WW 96
#define C4C 256
#define HWp (HH*WW)
#define NPIX (BB*HH*WW)
#define NTOT (BB*CC*HH*WW)
#define PP 4
#define SBG 16

// ---------------- scratch ----------------
__device__ float g_bn [SBG*64*HWp];
__device__ float g_res[SBG*64*HWp];
__device__ __align__(16) __nv_bfloat16 g_aH[SBG*HWp*64], g_aM[SBG*HWp*64];
__device__ __align__(16) __nv_bfloat16 g_yH[SBG*HWp*64], g_yM[SBG*HWp*64];
__device__ __align__(16) __nv_bfloat16 g_w1H[4*9*64*64], g_w1M[4*9*64*64];
__device__ __align__(16) __nv_bfloat16 g_w2H[4*9*64*64], g_w2M[4*9*64*64];
__device__ float g_Q[NTOT], g_K[NTOT], g_xl[NTOT], g_xr[NTOT], g_oL[NTOT], g_oR[NTOT];

__device__ __forceinline__ uint32_t smem_u32(const void* p) {
    uint32_t a;
    asm("{ .reg .u64 t; cvta.to.shared.u64 t, %1; cvt.u32.u64 %0, t; }" : "=r"(a) : "l"(p));
    return a;
}
__device__ __forceinline__ void ldm_x4(uint32_t* r, uint32_t addr) {
    asm volatile("ldmatrix.sync.aligned.m8n8.x4.shared.b16 {%0,%1,%2,%3}, [%4];"
        : "=r"(r[0]), "=r"(r[1]), "=r"(r[2]), "=r"(r[3]) : "r"(addr));
}
__device__ __forceinline__ void mma16816(float* d, const uint32_t* a, uint32_t b0, uint32_t b1) {
    asm volatile("mma.sync.aligned.m16n8k16.row.col.f32.bf16.bf16.f32 "
        "{%0,%1,%2,%3}, {%4,%5,%6,%7}, {%8,%9}, {%0,%1,%2,%3};"
        : "+f"(d[0]), "+f"(d[1]), "+f"(d[2]), "+f"(d[3])
        : "r"(a[0]), "r"(a[1]), "r"(a[2]), "r"(a[3]), "r"(b0), "r"(b1));
}
__device__ __forceinline__ void cp16(uint32_t dst, const void* src, bool pred) {
    asm volatile("cp.async.cg.shared.global [%0], [%1], 16, %2;"
        :: "r"(dst), "l"(src), "r"(pred ? 16 : 0) : "memory");
}
#define CP_COMMIT() asm volatile("cp.async.commit_group;" ::: "memory")
#define CP_WAIT0()  asm volatile("cp.async.wait_group 0;" ::: "memory")

__device__ __forceinline__ void split2(float x, __nv_bfloat16& h, __nv_bfloat16& m) {
    h = __float2bfloat16_rn(x);
    m = __float2bfloat16_rn(x - __bfloat162float(h));
}

// ---------------- fused BN + bf16 split ----------------
__global__ __launch_bounds__(256)
void bn_prep_kernel(const float* __restrict__ cl, const float* __restrict__ cr,
                    const float* __restrict__ gg, const float* __restrict__ bt,
                    const float* __restrict__ mn, const float* __restrict__ vr) {
    __shared__ float s[64][33];
    int z = blockIdx.y;
    int sb = z >> 2, g = z & 3;
    int side = sb >> 1, b = sb & 1;
    int px0 = blockIdx.x * 32;
    int tid = threadIdx.x;
    int px = tid & 31, icq = tid >> 5;
    const float* src = (side ? cr : cl) + ((size_t)b * C4C + g * 64) * HWp + px0;
    float* bdst = g_bn + ((size_t)sb * C4C + g * 64) * HWp + px0;
    #pragma unroll
    for (int j = 0; j < 8; j++) {
        int ic = icq * 8 + j;
        int ch = g * 64 + ic;
        float sc = gg[ch] * rsqrtf(vr[ch] + 1e-5f);
        float sh = bt[ch] - mn[ch] * sc;
        float v = fmaf(src[(size_t)ic * HWp + px], sc, sh);
        s[ic][px] = v;
        bdst[(size_t)ic * HWp + px] = v;
    }
    __syncthreads();
    int opx = tid >> 3, ic0 = (tid & 7) * 8;
    __nv_bfloat16 h[8], m[8];
    #pragma unroll
    for (int j = 0; j < 8; j++) split2(s[ic0 + j][opx], h[j], m[j]);
    size_t o = ((size_t)z * HWp + px0 + opx) * 64 + ic0;
    *(uint4*)(g_aH + o) = *(uint4*)h;
    *(uint4*)(g_aM + o) = *(uint4*)m;
}

// ---------------- prep weights ----------------
__global__ void prep_weights_kernel(const float* __restrict__ w1, const float* __restrict__ w2) {
    int idx = blockIdx.x * blockDim.x + threadIdx.x;
    if (idx >= 4*9*64*64) return;
    int ic  = idx & 63;
    int ocl = (idx >> 6) & 63;
    int rest = idx >> 12;
    int g = rest / 9, khw = rest % 9;
    size_t si = ((size_t)(g*64 + ocl) * 64 + ic) * 9 + khw;
    __nv_bfloat16 h, m;
    split2(w1[si], h, m); g_w1H[idx] = h; g_w1M[idx] = m;
    split2(w2[si], h, m); g_w2H[idx] = h; g_w2M[idx] = m;
}

// ---------------- mma.sync grouped conv3x3, halo-A + double-buffered B ----------------
#define A_TERM  29376
#define B_BASE  58752
#define B_BUF   18432
#define B_TERM  9216
#define CONV_SMEM 95616

template<int STAGE>
__global__ __launch_bounds__(256, 2)
void conv_mma_kernel(const float* __restrict__ bias) {
    extern __shared__ __align__(16) char smraw[];
    const int tid = threadIdx.x;
    const int warp = tid >> 5, lane = tid & 31;
    int z = blockIdx.z, sb = z >> 2, g = z & 3;
    int y0 = blockIdx.y * 4, x0 = blockIdx.x * 32;

    const __nv_bfloat16* A0 = (STAGE == 0) ? g_aH : g_yH;
    const __nv_bfloat16* A1 = (STAGE == 0) ? g_aM : g_yM;
    const __nv_bfloat16* B0 = (STAGE == 0) ? g_w1H : g_w2H;
    const __nv_bfloat16* B1 = (STAGE == 0) ? g_w1M : g_w2M;

    uint32_t sbase = smem_u32(smraw);

    for (int i = tid; i < 204 * 8; i += 256) {
        int hr = i >> 3, seg = i & 7;
        int hy = hr / 34, hx = hr % 34;
        int y = y0 - 1 + hy, x = x0 - 1 + hx;
        bool ok = (y >= 0) && (y < HH) && (x >= 0) && (x < WW);
        size_t si = ((size_t)z * HWp + (size_t)y * WW + x) * 8 + seg;
        uint32_t dst = sbase + hr * 144 + seg * 16;
        cp16(dst,          (const uint4*)A0 + (ok ? si : 0), ok);
        cp16(dst + A_TERM, (const uint4*)A1 + (ok ? si : 0), ok);
    }
    for (int i = tid; i < 512; i += 256) {
        int br = i >> 3, seg = i & 7;
        size_t si = (((size_t)g * 9 + 0) * 64 + br) * 8 + seg;
        uint32_t dst = sbase + B_BASE + br * 144 + seg * 16;
        cp16(dst,          (const uint4*)B0 + si, true);
        cp16(dst + B_TERM, (const uint4*)B1 + si, true);
    }
    CP_COMMIT();

    float acc[8][4];
    #pragma unroll
    for (int nb = 0; nb < 8; nb++)
        #pragma unroll
        for (int e = 0; e < 4; e++) acc[nb][e] = 0.f;

    int m0 = warp * 16;
    int pxr = (m0 + (lane & 15)) >> 5;
    int pxc = (m0 + (lane & 15)) & 31;
    uint32_t a_half = (lane >> 4) * 16;
    uint32_t b_row = (lane & 7) + ((lane >> 1) & 8);
    uint32_t b_k   = ((lane >> 3) & 1) * 8;

    CP_WAIT0();
    __syncthreads();

    int buf = 0;
    #pragma unroll 1
    for (int tap = 0; tap < 9; tap++) {
        if (tap < 8) {
            int nb = buf ^ 1;
            for (int i = tid; i < 512; i += 256) {
                int br = i >> 3, seg = i & 7;
                size_t si = (((size_t)g * 9 + tap + 1) * 64 + br) * 8 + seg;
                uint32_t dst = sbase + B_BASE + nb * B_BUF + br * 144 + seg * 16;
                cp16(dst,          (const uint4*)B0 + si, true);
                cp16(dst + B_TERM, (const uint4*)B1 + si, true);
            }
            CP_COMMIT();
        }

        int hy = pxr + tap / 3;
        int hx = pxc + tap % 3;
        uint32_t a_addr = sbase + (uint32_t)(hy * 34 + hx) * 144 + a_half;
        uint32_t bb = sbase + B_BASE + buf * B_BUF;

        #pragma unroll
        for (int k = 0; k < 4; k++) {
            uint32_t ah[4], am[4];
            ldm_x4(ah, a_addr          + k * 32);
            ldm_x4(am, a_addr + A_TERM + k * 32);
            #pragma unroll
            for (int nb2 = 0; nb2 < 4; nb2++) {
                uint32_t boff = ((nb2 * 16 + b_row) * 144) + (k * 16 + b_k) * 2;
                uint32_t bh[4], bm[4];
                ldm_x4(bh, bb + boff);
                ldm_x4(bm, bb + B_TERM + boff);
                mma16816(acc[2*nb2    ], ah, bh[0], bh[1]);
                mma16816(acc[2*nb2    ], ah, bm[0], bm[1]);
                mma16816(acc[2*nb2    ], am, bh[0], bh[1]);
                mma16816(acc[2*nb2 + 1], ah, bh[2], bh[3]);
                mma16816(acc[2*nb2 + 1], ah, bm[2], bm[3]);
                mma16816(acc[2*nb2 + 1], am, bh[2], bh[3]);
            }
        }

        if (tap < 8) {
            CP_WAIT0();
            __syncthreads();
            buf ^= 1;
        }
    }

    int tq = lane >> 2, tr = lane & 3;
    __syncthreads();

    if (STAGE == 0) {
        float* stg = (float*)smraw;
        #pragma unroll
        for (int nb = 0; nb < 8; nb++) {
            int col = nb * 8 + tr * 2;
            float b0 = bias[g * 64 + col], b1 = bias[g * 64 + col + 1];
            float v0 = acc[nb][0] + b0, v1 = acc[nb][1] + b1;
            float v2 = acc[nb][2] + b0, v3 = acc[nb][3] + b1;
            v0 = v0 > 0.f ? v0 : 0.1f * v0;
            v1 = v1 > 0.f ? v1 : 0.1f * v1;
            v2 = v2 > 0.f ? v2 : 0.1f * v2;
            v3 = v3 > 0.f ? v3 : 0.1f * v3;
            stg[(m0 + tq    ) * 65 + col    ] = v0;
            stg[(m0 + tq    ) * 65 + col + 1] = v1;
            stg[(m0 + 8 + tq) * 65 + col    ] = v2;
            stg[(m0 + 8 + tq) * 65 + col + 1] = v3;
        }
        __syncthreads();
        for (int i = tid; i < 1024; i += 256) {
            int ar = i >> 3, seg = i & 7;
            __nv_bfloat16 h[8], m[8];
            #pragma unroll
            for (int j = 0; j < 8; j++) split2(stg[ar * 65 + seg * 8 + j], h[j], m[j]);
            size_t o = ((size_t)z * HWp + (size_t)(y0 + (ar >> 5)) * WW + (x0 + (ar & 31))) * 8 + seg;
            ((uint4*)g_yH)[o] = *(uint4*)h;
            ((uint4*)g_yM)[o] = *(uint4*)m;
        }
    } else {
        float* stg = (float*)smraw;
        #pragma unroll
        for (int nb = 0; nb < 8; nb++) {
            int col = nb * 8 + tr * 2;
            float b0 = bias[g * 64 + col], b1 = bias[g * 64 + col + 1];
            stg[(col    ) * 128 + m0 + tq    ] = acc[nb][0] + b0;
            stg[(col + 1) * 128 + m0 + tq    ] = acc[nb][1] + b1;
            stg[(col    ) * 128 + m0 + 8 + tq] = acc[nb][2] + b0;
            stg[(col + 1) * 128 + m0 + 8 + tq] = acc[nb][3] + b1;
        }
        __syncthreads();
        for (int i = tid; i < 64 * 128; i += 256) {
            int oc = i >> 7, px = i & 127;
            size_t gi = ((size_t)sb * C4C + g * 64 + oc) * HWp
                      + (size_t)(y0 + (px >> 5)) * WW + (x0 + (px & 31));
            g_res[gi] = stg[oc * 128 + px] + g_bn[gi];
        }
    }
}

// ---------------- transposes ----------------
__global__ void transpose_in_kernel(const float* __restrict__ in, int which) {
    __shared__ float tile[32][33];
    float* out = which ? g_xr : g_xl;
    int b = blockIdx.z;
    const float* inb = in + (size_t)b * CC * HWp;
    float* outb      = out + (size_t)b * HWp * CC;
    int p0 = blockIdx.x * 32, c0 = blockIdx.y * 32;
    int tx = threadIdx.x, ty = threadIdx.y;
    #pragma unroll
    for (int i = 0; i < 32; i += 8)
        tile[ty + i][tx] = inb[(size_t)(c0 + ty + i) * HWp + p0 + tx];
    __syncthreads();
    #pragma unroll
    for (int i = 0; i < 32; i += 8)
        outb[(size_t)(p0 + ty + i) * CC + c0 + tx] = tile[tx][ty + i];
}
__global__ void transpose_out_kernel(float* __restrict__ outbase, int which) {
    __shared__ float tile[32][33];
    const float* in = which ? g_oR : g_oL;
    float* out = outbase + (size_t)which * NTOT;
    int b = blockIdx.z;
    const float* inb = in + (size_t)b * HWp * CC;
    float* outb      = out + (size_t)b * CC * HWp;
    int c0 = blockIdx.x * 32, p0 = blockIdx.y * 32;
    int tx = threadIdx.x, ty = threadIdx.y;
    #pragma unroll
    for (int i = 0; i < 32; i += 8)
        tile[ty + i][tx] = inb[(size_t)(p0 + ty + i) * CC + c0 + tx];
    __syncthreads();
    #pragma unroll
    for (int i = 0; i < 32; i += 8)
        outb[(size_t)(c0 + ty + i) * HWp + p0 + tx] = tile[tx][ty + i];
}

// ---------------- f32x2 helpers ----------------
__device__ __forceinline__ uint64_t pack2(float lo, float hi) {
    uint64_t r; asm("mov.b64 %0, {%1, %2};" : "=l"(r) : "f"(lo), "f"(hi)); return r;
}
__device__ __forceinline__ void unpack2(uint64_t v, float& lo, float& hi) {
    asm("mov.b64 {%0, %1}, %2;" : "=f"(lo), "=f"(hi) : "l"(v));
}
__device__ __forceinline__ void ffma2(uint64_t& d, uint64_t a, uint64_t b) {
    asm("fma.rn.f32x2 %0, %1, %2, %0;" : "+l"(d) : "l"(a), "l"(b));
}

// ---------------- grouped 1x1 conv -> Q/K NHWC ----------------
__global__ __launch_bounds__(256)
void conv1x1_kernel(const float* __restrict__ bq_w, const float* __restrict__ bq_b,
                    const float* __restrict__ bs_w, const float* __restrict__ bs_b) {
    __shared__ float in_s[64][64];
    __shared__ float w_sh[16][64];
    int side = blockIdx.z, g = blockIdx.y;
    int p0 = blockIdx.x * 64;
    int b = p0 / HWp;
    int tid = threadIdx.x;
    const float* wsrc = side ? bs_w : bq_w;
    const float* bsrc = side ? bs_b : bq_b;
    for (int i = tid; i < 16*64; i += 256) {
        int oc = i >> 6, ic = i & 63;
        w_sh[oc][ic] = wsrc[(g*16 + oc)*64 + ic];
    }
    const float* resb = g_res + ((size_t)(side*BB + b) * C4C + g*64) * HWp + (p0 - b*HWp);
    for (int i = tid; i < 64*64; i += 256) {
        int ch = i >> 6, px = i & 63;
        in_s[ch][px] = resb[(size_t)ch * HWp + px];
    }
    __syncthreads();
    int oc = tid & 15, pq = tid >> 4;
    uint64_t acc[2] = {0ull, 0ull};
    #pragma unroll 8
    for (int ic = 0; ic < 64; ic++) {
        float wv = w_sh[oc][ic];
        uint64_t ww = pack2(wv, wv);
        const uint64_t* irow = (const uint64_t*)&in_s[ic][pq*4];
        ffma2(acc[0], irow[0], ww);
        ffma2(acc[1], irow[1], ww);
    }
    float bv = bsrc[g*16 + oc];
    float* o = side ? g_K : g_Q;
    int ocg = g*16 + oc;
    #pragma unroll
    for (int j = 0; j < 2; j++) {
        float lo, hi;
        unpack2(acc[j], lo, hi);
        int px = pq*4 + 2*j;
        o[(size_t)(p0 + px    ) * CC + ocg] = lo + bv;
        o[(size_t)(p0 + px + 1) * CC + ocg] = hi + bv;
    }
}

// ---------------- attention v2: 2 pixels/block, branchless value loop ----------------
__global__ __launch_bounds__(128)
void attn_kernel(const int* __restrict__ d_left, const int* __restrict__ d_right) {
    __shared__ __align__(16) float q_s[2][64];
    __shared__ __align__(16) float k_s[2][64];
    __shared__ __align__(8)  float2 sw_s[2][64];   // {s1*mask, s2*mask}
    __shared__ int   cd_s[2][64];                  // clamped row offset * CC
    __shared__ float red[2][2];

    int tid  = threadIdx.x;
    int grp  = tid >> 6;          // 0/1 pixel group
    int t    = tid & 63;
    int wig  = (tid >> 5) & 1;    // warp within group
    int pix  = blockIdx.x * 2 + grp;

    int b  = pix / HWp;
    int hp = pix % HWp;
    int h  = hp / WW, w = hp % WW;

    q_s[grp][t] = g_Q[(size_t)pix * CC + t];
    k_s[grp][t] = g_K[(size_t)pix * CC + t];

    int dl = d_left[pix], dr = d_right[pix];
    int c1 = max(w - dl, 0);
    int c2 = min(w + dr, WW - 1);
    bool rowok  = (h < HH - PP);
    bool valid1 = rowok && (c1 < WW - PP);
    bool valid2 = rowok && (c2 < WW - PP);
    __syncthreads();

    int a = t >> 3, bb2 = t & 7;
    int y  = h + a - PP;
    int x1 = c1 + bb2 - PP;
    int x2 = c2 + bb2 - PP;
    bool in1 = valid1 && (y >= 0) && (y < HH) && (x1 >= 0) && (x1 < WW);
    bool in2 = valid2 && (y >= 0) && (y < HH) && (x2 >= 0) && (x2 < WW);

    float r1 = 0.f, r2 = 0.f;
    if (in1) {
        const float4* kr = (const float4*)(g_K + ((size_t)b*HWp + (size_t)y*WW + x1) * CC);
        const float4* qv = (const float4*)q_s[grp];
        #pragma unroll
        for (int i = 0; i < 16; i++) {
            float4 kv = kr[i]; float4 q4 = qv[i];
            r1 += q4.x*kv.x + q4.y*kv.y + q4.z*kv.z + q4.w*kv.w;
        }
    }
    if (in2) {
        const float4* qr = (const float4*)(g_Q + ((size_t)b*HWp + (size_t)y*WW + x2) * CC);
        const float4* k4v = (const float4*)k_s[grp];
        #pragma unroll
        for (int i = 0; i < 16; i++) {
            float4 qv2 = qr[i]; float4 k4 = k4v[i];
            r2 += k4.x*qv2.x + k4.y*qv2.y + k4.z*qv2.z + k4.w*qv2.w;
        }
    }

    // group-wise softmax (64 lanes = 2 warps)
    float m1 = r1, m2 = r2;
    #pragma unroll
    for (int o = 16; o; o >>= 1) {
        m1 = fmaxf(m1, __shfl_xor_sync(0xffffffffu, m1, o));
        m2 = fmaxf(m2, __shfl_xor_sync(0xffffffffu, m2, o));
    }
    if ((t & 31) == 0) red[grp][wig] = m1;
    __syncthreads();
    m1 = fmaxf(red[grp][0], red[grp][1]);
    __syncthreads();
    if ((t & 31) == 0) red[grp][wig] = m2;
    __syncthreads();
    m2 = fmaxf(red[grp][0], red[grp][1]);
    __syncthreads();

    float e1 = __expf(r1 - m1);
    float e2 = __expf(r2 - m2);
    float z1 = e1, z2 = e2;
    #pragma unroll
    for (int o = 16; o; o >>= 1) {
        z1 += __shfl_xor_sync(0xffffffffu, z1, o);
        z2 += __shfl_xor_sync(0xffffffffu, z2, o);
    }
    if ((t & 31) == 0) red[grp][wig] = z1;
    __syncthreads();
    z1 = red[grp][0] + red[grp][1];
    __syncthreads();
    if ((t & 31) == 0) red[grp][wig] = z2;
    __syncthreads();
    z2 = red[grp][0] + red[grp][1];

    // masked weights: zero when r2l coord invalid (value gathers both use r2l coords)
    float msk = in1 ? 1.f : 0.f;
    sw_s[grp][t] = make_float2(msk * e1 / z1, msk * e2 / z2);
    cd_s[grp][t] = in1 ? (y * WW + x1) * CC : 0;
    __syncthreads();

    // branchless value aggregation, unroll 8 for load batching
    const float* xrb = g_xr + (size_t)b * HWp * CC;
    const float* xlb = g_xl + (size_t)b * HWp * CC;
    float accL = 0.f, accR = 0.f;
    #pragma unroll 8
    for (int k = 0; k < 64; k++) {
        float2 sw = sw_s[grp][k];
        int cd = cd_s[grp][k];
        float vr = xrb[cd + t];
        float vl = xlb[cd + t];
        accL = fmaf(sw.x, vr, accL);
        accR = fmaf(sw.y, vl, accR);
    }
    float VL = (w - dl >= 0)    ? 1.f : 0.f;
    float VR = (w + dr <= WW-1) ? 1.f : 0.f;
    size_t oi = (size_t)pix * CC + t;
    g_oL[oi] = xlb[(size_t)hp * CC + t] + VL * accL;
    g_oR[oi] = xrb[(size_t)hp * CC + t] + VR * accR;
}

// ---------------- launch ----------------
extern "C" void kernel_launch(void* const* d_in, const int* in_sizes, int n_in,
                              void* d_out, int out_size) {
    (void)n_in; (void)out_size;
    const float *xl, *xr, *cl, *cr, *bg, *bbeta, *bm, *bv;
    const float *w1, *b1, *w2, *b2, *bqw, *bqb, *bsw, *bsb;
    const int *dl, *dr;

    if (in_sizes[4] == BB*HH*WW) {
        xl  = (const float*)d_in[0];  xr  = (const float*)d_in[1];
        cl  = (const float*)d_in[2];  cr  = (const float*)d_in[3];
        dl  = (const int*)  d_in[4];  dr  = (const int*)  d_in[5];
        bg  = (const float*)d_in[6];  bbeta=(const float*)d_in[7];
        bm  = (const float*)d_in[8];  bv  = (const float*)d_in[9];
        w1  = (const float*)d_in[10]; b1  = (const float*)d_in[11];
        w2  = (const float*)d_in[12]; b2  = (const float*)d_in[13];
        bqw = (const float*)d_in[14]; bqb = (const float*)d_in[15];
        bsw = (const float*)d_in[16]; bsb = (const float*)d_in[17];
    } else {
        xl  = (const float*)d_in[0];  xr  = (const float*)d_in[1];
        cl  = (const float*)d_in[2];  cr  = (const float*)d_in[3];
        bg  = (const float*)d_in[4];  bbeta=(const float*)d_in[5];
        bm  = (const float*)d_in[6];  bv  = (const float*)d_in[7];
        w1  = (const float*)d_in[8];  b1  = (const float*)d_in[9];
        w2  = (const float*)d_in[10]; b2  = (const float*)d_in[11];
        bqw = (const float*)d_in[12]; bqb = (const float*)d_in[13];
        bsw = (const float*)d_in[14]; bsb = (const float*)d_in[15];
        dl  = (const int*)  d_in[16]; dr  = (const int*)  d_in[17];
    }

    cudaFuncSetAttribute(conv_mma_kernel<0>, cudaFuncAttributeMaxDynamicSharedMemorySize, CONV_SMEM);
    cudaFuncSetAttribute(conv_mma_kernel<1>, cudaFuncAttributeMaxDynamicSharedMemorySize, CONV_SMEM);

    dim3 tb(32, 8);
    dim3 cgrid(WW/32, HH/4, SBG);

    bn_prep_kernel<<<dim3(HWp/32, SBG), 256>>>(cl, cr, bg, bbeta, bm, bv);
    prep_weights_kernel<<<(4*9*64*64 + 255)/256, 256>>>(w1, w2);
    transpose_in_kernel<<<dim3(HWp/32, CC/32, BB), tb>>>(xl, 0);
    transpose_in_kernel<<<dim3(HWp/32, CC/32, BB), tb>>>(xr, 1);

    conv_mma_kernel<0><<<cgrid, 256, CONV_SMEM>>>(b1);
    conv_mma_kernel<1><<<cgrid, 256, CONV_SMEM>>>(b2);

    conv1x1_kernel<<<dim3(BB*HWp/64, 4, 2), 256>>>(bqw, bqb, bsw, bsb);
    attn_kernel<<<NPIX/2, 128>>>(dl, dr);

    transpose_out_kernel<<<dim3(CC/32, HWp/32, BB), tb>>>((float*)d_out, 0);
    transpose_out_kernel<<<dim3(CC/32, HWp/32, BB), tb>>>((float*)d_out, 1);
}